// round 1
// baseline (speedup 1.0000x reference)
#include <cuda_runtime.h>
#include <cuda_fp16.h>
#include <cstdint>

#define N_NODES 4096
#define MAXH 4

// ---------------- scratch (static device globals; no allocation) ----------------
__device__ unsigned g_maskw[N_NODES * 128];            // 2 MB adjacency bitmask
__device__ float    g_hfeat[MAXH * N_NODES * 64];      // per-head features fp32
__device__ __half   g_h16T [MAXH * 64 * N_NODES];      // per-head features fp16, transposed [h][o][n]
__device__ float    g_el[MAXH * N_NODES], g_er[MAXH * N_NODES];
__device__ float    g_P [MAXH * N_NODES], g_Q [MAXH * N_NODES], g_T [MAXH * N_NODES];
__device__ float    g_G1[MAXH * N_NODES], g_G2[MAXH * N_NODES];
__device__ float    g_C[MAXH];
__device__ float    g_buf0[N_NODES * 256];
__device__ float    g_buf1[N_NODES * 256];

// ---------------- adjacency -> bitmask ----------------
__global__ void k_mask(const int* __restrict__ adj, unsigned* __restrict__ maskw) {
    int n = blockIdx.x;
    int tid = threadIdx.x;
    const int* row = adj + (size_t)n * N_NODES;
#pragma unroll
    for (int it = 0; it < 4; it++) {
        int m = it * 1024 + tid;
        unsigned b = __ballot_sync(0xffffffffu, row[m] > 0);
        if ((tid & 31) == 0) maskw[n * 128 + (m >> 5)] = b;
    }
}

// ---------------- feature GEMM: h[h][n][o] = in[n][:K] @ W[h][:K][o]  (fp32 + fp16T copy) ----------------
__global__ void k_feat(const float* __restrict__ in, const float* __restrict__ W,
                       float* __restrict__ hfeat, __half* __restrict__ h16T, int K) {
    __shared__ float As[64][17];
    __shared__ float Bs[16][68];
    const int h  = blockIdx.y;
    const int nb = blockIdx.x * 64;
    const int tid = threadIdx.x;
    const int tx = tid & 15, ty = tid >> 4;
    const float* Wh = W + (size_t)h * K * 64;

    float acc[4][4];
#pragma unroll
    for (int i = 0; i < 4; i++)
#pragma unroll
        for (int j = 0; j < 4; j++) acc[i][j] = 0.f;

    for (int k0 = 0; k0 < K; k0 += 16) {
#pragma unroll
        for (int i = 0; i < 4; i++) {
            int idx = tid + i * 256;           // 0..1023
            int r = idx >> 4, c = idx & 15;
            As[r][c] = in[(size_t)(nb + r) * K + k0 + c];
        }
#pragma unroll
        for (int i = 0; i < 4; i++) {
            int idx = tid + i * 256;
            int r = idx >> 6, c = idx & 63;
            Bs[r][c] = Wh[(size_t)(k0 + r) * 64 + c];
        }
        __syncthreads();
#pragma unroll
        for (int kk = 0; kk < 16; kk++) {
            float a[4], b[4];
#pragma unroll
            for (int i = 0; i < 4; i++) a[i] = As[ty * 4 + i][kk];
#pragma unroll
            for (int j = 0; j < 4; j++) b[j] = Bs[kk][tx * 4 + j];
#pragma unroll
            for (int i = 0; i < 4; i++)
#pragma unroll
                for (int j = 0; j < 4; j++) acc[i][j] = fmaf(a[i], b[j], acc[i][j]);
        }
        __syncthreads();
    }
#pragma unroll
    for (int i = 0; i < 4; i++) {
        int n = nb + ty * 4 + i;
        float4 v = make_float4(acc[i][0], acc[i][1], acc[i][2], acc[i][3]);
        *reinterpret_cast<float4*>(&hfeat[((size_t)h * N_NODES + n) * 64 + tx * 4]) = v;
#pragma unroll
        for (int jj = 0; jj < 4; jj++)
            h16T[((size_t)h * 64 + tx * 4 + jj) * N_NODES + n] = __float2half_rn(acc[i][jj]);
    }
}

// ---------------- e_l, e_r dot products (one warp per (h,n)) ----------------
__global__ void k_elr(const float* __restrict__ hfeat, const float* __restrict__ a,
                      float* __restrict__ el, float* __restrict__ er) {
    const int lane = threadIdx.x & 31;
    const int idx  = blockIdx.x * 8 + (threadIdx.x >> 5);   // idx = h*N + n
    const int h    = idx >> 12;
    const float* hp = hfeat + (size_t)idx * 64;
    const float* ap = a + h * 128;
    float v0 = hp[lane], v1 = hp[lane + 32];
    float sl = v0 * ap[lane]      + v1 * ap[lane + 32];
    float sr = v0 * ap[64 + lane] + v1 * ap[96 + lane];
#pragma unroll
    for (int o = 16; o; o >>= 1) {
        sl += __shfl_xor_sync(0xffffffffu, sl, o);
        sr += __shfl_xor_sync(0xffffffffu, sr, o);
    }
    if (lane == 0) { el[idx] = sl; er[idx] = sr; }
}

// ---------------- per-head max of e_r ----------------
__global__ void k_max(const float* __restrict__ er, float* __restrict__ C) {
    const int h = blockIdx.x;
    __shared__ float sm[32];
    float m = -3.4e38f;
    for (int i = threadIdx.x; i < N_NODES; i += blockDim.x) m = fmaxf(m, er[h * N_NODES + i]);
#pragma unroll
    for (int o = 16; o; o >>= 1) m = fmaxf(m, __shfl_xor_sync(0xffffffffu, m, o));
    if ((threadIdx.x & 31) == 0) sm[threadIdx.x >> 5] = m;
    __syncthreads();
    if (threadIdx.x < 32) {
        float v = sm[threadIdx.x];
#pragma unroll
        for (int o = 16; o; o >>= 1) v = fmaxf(v, __shfl_xor_sync(0xffffffffu, v, o));
        if (threadIdx.x == 0) C[h] = v;
    }
}

// ---------------- P,Q,T,G1,G2 (O(N) exps — replaces the N^2 exp of naive softmax) ----------------
__global__ void k_pqg(const float* __restrict__ el, const float* __restrict__ er,
                      const float* __restrict__ C,
                      float* __restrict__ P, float* __restrict__ Q, float* __restrict__ T,
                      float* __restrict__ G1, float* __restrict__ G2) {
    const int i = blockIdx.x * 256 + threadIdx.x;
    const int h = i >> 12;
    const float c  = C[h];
    const float e_r = er[i], e_l = el[i];
    P[i] = expf(e_r - c);
    Q[i] = expf(0.2f * (e_r - c));
    T[i] = -e_l;
    const float z = e_l + c;
    if (z > 0.f) { G1[i] = 1.f;               G2[i] = expf(-0.8f * z); }
    else         { G1[i] = expf(0.8f * z);    G2[i] = 1.f; }
}

// ---------------- fused flash-style attention: out = (W @ h) / rowsum(W) ----------------
struct AttnSmem {
    __half Ws [128 * 136];   // 34816 B, padded for conflict-free LDSM
    __half hTs[64 * 136];    // 17408 B, hT[o][m]
    float  Ps[128], Qs[128], Es[128], rowsum[128];
};

__device__ __forceinline__ unsigned smem_u32(const void* p) {
    return (unsigned)__cvta_generic_to_shared(p);
}

__global__ void __launch_bounds__(256) k_attn(
    const __half* __restrict__ h16T,
    const float* __restrict__ Pg, const float* __restrict__ Qg,
    const float* __restrict__ Eg, const float* __restrict__ Tg,
    const float* __restrict__ G1g, const float* __restrict__ G2g,
    const unsigned* __restrict__ maskw,
    float* __restrict__ out, int outStride, int applyElu) {
    extern __shared__ char smem_raw[];
    AttnSmem& S = *reinterpret_cast<AttnSmem*>(smem_raw);

    const int head = blockIdx.y;
    const int n0   = blockIdx.x * 128;
    const int tid  = threadIdx.x;
    const int lane = tid & 31, warp = tid >> 5;
    const int brow = tid >> 1;         // W-build row (2 threads/row)
    const int par  = tid & 1;          // interleaved column parity

    const int hb = head * N_NODES;
    const float t_r  = Tg [hb + n0 + brow];
    const float G1_r = G1g[hb + n0 + brow];
    const float G2_r = G2g[hb + n0 + brow];
    float rs = 0.f;

    float acc[8][4];
#pragma unroll
    for (int i = 0; i < 8; i++)
#pragma unroll
        for (int j = 0; j < 4; j++) acc[i][j] = 0.f;

    const __half*   hT   = h16T + (size_t)head * 64 * N_NODES;
    const unsigned* mrow = maskw + (size_t)(n0 + brow) * 128;

    for (int j = 0; j < N_NODES / 128; j++) {
        const int m0 = j * 128;
        __syncthreads();
        // load h tile [64 o][128 m] (transposed layout) -> smem
#pragma unroll
        for (int i = 0; i < 4; i++) {
            int idx = tid + i * 256;
            int r = idx >> 4, c = idx & 15;
            *reinterpret_cast<uint4*>(&S.hTs[r * 136 + c * 8]) =
                *reinterpret_cast<const uint4*>(hT + (size_t)r * N_NODES + m0 + c * 8);
        }
        if (tid < 128) {
            S.Ps[tid] = Pg[hb + m0 + tid];
            S.Qs[tid] = Qg[hb + m0 + tid];
            S.Es[tid] = Eg[hb + m0 + tid];
        }
        uint4 mwv = *reinterpret_cast<const uint4*>(mrow + (m0 >> 5));
        __syncthreads();

        // ---- build W tile (no exp: compare + select + mask) ----
        {
            unsigned w[4] = {mwv.x, mwv.y, mwv.z, mwv.w};
            __half* wr = &S.Ws[brow * 136];
#pragma unroll
            for (int i = 0; i < 4; i++) {
#pragma unroll
                for (int b = 0; b < 16; b++) {
                    const int bit = 2 * b + par;
                    const int m = i * 32 + bit;
                    float v = (S.Es[m] > t_r) ? (G1_r * S.Ps[m]) : (G2_r * S.Qs[m]);
                    v = ((w[i] >> bit) & 1u) ? v : 0.f;
                    __half hv = __float2half_rn(v);
                    wr[m] = hv;
                    rs += __half2float(hv);   // keep denominator consistent with fp16 numerator
                }
            }
        }
        __syncthreads();

        // ---- MMA: [128x128] @ [128x64], fp16 -> fp32 ----
#pragma unroll
        for (int kc = 0; kc < 8; kc++) {
            unsigned a0, a1, a2, a3;
            int arow = warp * 16 + (lane & 7) + ((lane >> 3) & 1) * 8;
            int acol = kc * 16 + (lane >> 4) * 8;
            unsigned aaddr = smem_u32(&S.Ws[arow * 136 + acol]);
            asm volatile("ldmatrix.sync.aligned.m8n8.x4.shared.b16 {%0,%1,%2,%3}, [%4];\n"
                         : "=r"(a0), "=r"(a1), "=r"(a2), "=r"(a3) : "r"(aaddr));
#pragma unroll
            for (int nc = 0; nc < 8; nc++) {
                const __half* bp = &S.hTs[(nc * 8 + (lane >> 2)) * 136 + kc * 16 + 2 * (lane & 3)];
                unsigned b0 = *reinterpret_cast<const unsigned*>(bp);
                unsigned b1 = *reinterpret_cast<const unsigned*>(bp + 8);
                asm volatile(
                    "mma.sync.aligned.m16n8k16.row.col.f32.f16.f16.f32 "
                    "{%0,%1,%2,%3}, {%4,%5,%6,%7}, {%8,%9}, {%0,%1,%2,%3};\n"
                    : "+f"(acc[nc][0]), "+f"(acc[nc][1]), "+f"(acc[nc][2]), "+f"(acc[nc][3])
                    : "r"(a0), "r"(a1), "r"(a2), "r"(a3), "r"(b0), "r"(b1));
            }
        }
    }

    // ---- combine rowsums ----
    __syncthreads();
    if (par == 0) S.rowsum[brow] = rs;
    __syncthreads();
    if (par == 1) S.rowsum[brow] += rs;
    __syncthreads();

    // ---- epilogue: divide, ELU, store ----
    const int r_lo = warp * 16 + (lane >> 2);
    const float inv_lo = 1.f / S.rowsum[r_lo];
    const float inv_hi = 1.f / S.rowsum[r_lo + 8];
    float* obase = out + (size_t)n0 * outStride + head * 64;
#pragma unroll
    for (int nc = 0; nc < 8; nc++) {
        int col = nc * 8 + 2 * (lane & 3);
        float o0 = acc[nc][0] * inv_lo, o1 = acc[nc][1] * inv_lo;
        float o2 = acc[nc][2] * inv_hi, o3 = acc[nc][3] * inv_hi;
        if (applyElu) {
            o0 = o0 > 0.f ? o0 : expm1f(o0);
            o1 = o1 > 0.f ? o1 : expm1f(o1);
            o2 = o2 > 0.f ? o2 : expm1f(o2);
            o3 = o3 > 0.f ? o3 : expm1f(o3);
        }
        *reinterpret_cast<float2*>(obase + (size_t)r_lo * outStride + col)       = make_float2(o0, o1);
        *reinterpret_cast<float2*>(obase + (size_t)(r_lo + 8) * outStride + col) = make_float2(o2, o3);
    }
}

// ---------------- host orchestration ----------------
static void run_layer(const float* in, int K, const float* W, const float* a, int H,
                      float* outp, int outStride, int applyElu,
                      float* hfeat, __half* h16T, float* el, float* er, float* C,
                      float* P, float* Q, float* T, float* G1, float* G2, unsigned* maskw) {
    k_feat<<<dim3(64, H), 256>>>(in, W, hfeat, h16T, K);
    k_elr <<<H * (N_NODES / 8), 256>>>(hfeat, a, el, er);
    k_max <<<H, 1024>>>(er, C);
    k_pqg <<<H * (N_NODES / 256), 256>>>(el, er, C, P, Q, T, G1, G2);
    k_attn<<<dim3(N_NODES / 128, H), 256, sizeof(AttnSmem)>>>(
        h16T, P, Q, er, T, G1, G2, maskw, outp, outStride, applyElu);
}

extern "C" void kernel_launch(void* const* d_in, const int* in_sizes, int n_in,
                              void* d_out, int out_size) {
    (void)in_sizes; (void)n_in; (void)out_size;
    const float* x  = (const float*)d_in[0];
    const int*   adj = (const int*)d_in[1];
    const float* W0 = (const float*)d_in[2];
    const float* a0 = (const float*)d_in[3];
    const float* W1 = (const float*)d_in[4];
    const float* a1 = (const float*)d_in[5];
    const float* W2 = (const float*)d_in[6];
    const float* a2 = (const float*)d_in[7];

    cudaFuncSetAttribute(k_attn, cudaFuncAttributeMaxDynamicSharedMemorySize,
                         (int)sizeof(AttnSmem));

    void *p_maskw, *p_hfeat, *p_h16T, *p_el, *p_er, *p_C, *p_P, *p_Q, *p_T, *p_G1, *p_G2,
         *p_buf0, *p_buf1;
    cudaGetSymbolAddress(&p_maskw, g_maskw);
    cudaGetSymbolAddress(&p_hfeat, g_hfeat);
    cudaGetSymbolAddress(&p_h16T,  g_h16T);
    cudaGetSymbolAddress(&p_el,    g_el);
    cudaGetSymbolAddress(&p_er,    g_er);
    cudaGetSymbolAddress(&p_C,     g_C);
    cudaGetSymbolAddress(&p_P,     g_P);
    cudaGetSymbolAddress(&p_Q,     g_Q);
    cudaGetSymbolAddress(&p_T,     g_T);
    cudaGetSymbolAddress(&p_G1,    g_G1);
    cudaGetSymbolAddress(&p_G2,    g_G2);
    cudaGetSymbolAddress(&p_buf0,  g_buf0);
    cudaGetSymbolAddress(&p_buf1,  g_buf1);

    unsigned* maskw = (unsigned*)p_maskw;
    float* hfeat = (float*)p_hfeat;  __half* h16T = (__half*)p_h16T;
    float* el = (float*)p_el;  float* er = (float*)p_er;  float* C = (float*)p_C;
    float* P = (float*)p_P;    float* Q = (float*)p_Q;    float* T = (float*)p_T;
    float* G1 = (float*)p_G1;  float* G2 = (float*)p_G2;
    float* buf0 = (float*)p_buf0;  float* buf1 = (float*)p_buf1;

    k_mask<<<N_NODES, 1024>>>(adj, maskw);

    run_layer(x,    128, W0, a0, 4, buf0,           256, 1,
              hfeat, h16T, el, er, C, P, Q, T, G1, G2, maskw);
    run_layer(buf0, 256, W1, a1, 4, buf1,           256, 1,
              hfeat, h16T, el, er, C, P, Q, T, G1, G2, maskw);
    run_layer(buf1, 256, W2, a2, 1, (float*)d_out,   64, 0,
              hfeat, h16T, el, er, C, P, Q, T, G1, G2, maskw);
}

// round 3
// speedup vs baseline: 1.4399x; 1.4399x over previous
#include <cuda_runtime.h>
#include <cuda_fp16.h>
#include <cstdint>

#define N_NODES 4096
#define MAXH 4

// ---------------- scratch (static device globals; no allocation) ----------------
__device__ unsigned g_maskw[N_NODES * 128];            // 2 MB adjacency bitmask
__device__ float    g_hfeat[MAXH * N_NODES * 64];      // per-head features fp32
__device__ __half   g_h16T [MAXH * 64 * N_NODES];      // per-head features fp16, transposed [h][o][n]
__device__ float    g_el[MAXH * N_NODES], g_er[MAXH * N_NODES];
__device__ float    g_P [MAXH * N_NODES], g_Q [MAXH * N_NODES];
__device__ float    g_G1[MAXH * N_NODES], g_G2[MAXH * N_NODES];
__device__ float    g_C[MAXH];
__device__ float    g_buf0[N_NODES * 256];
__device__ float    g_buf1[N_NODES * 256];
__device__ float    g_part[4 * N_NODES * 68];          // split-m partials for layer 2

// ---------------- adjacency -> bitmask ----------------
__global__ void k_mask(const int* __restrict__ adj, unsigned* __restrict__ maskw) {
    int n = blockIdx.x;
    int tid = threadIdx.x;
    const int* row = adj + (size_t)n * N_NODES;
#pragma unroll
    for (int it = 0; it < 4; it++) {
        int m = it * 1024 + tid;
        unsigned b = __ballot_sync(0xffffffffu, row[m] > 0);
        if ((tid & 31) == 0) maskw[n * 128 + (m >> 5)] = b;
    }
}

// ---------------- feature GEMM: h[h][n][o] = in[n][:K] @ W[h][:K][o] ----------------
__global__ void k_feat(const float* __restrict__ in, const float* __restrict__ W,
                       float* __restrict__ hfeat, __half* __restrict__ h16T, int K) {
    __shared__ float Ast[16][68];   // k-major (transposed) for vector LDS
    __shared__ float Bs[16][68];
    const int h  = blockIdx.y;
    const int nb = blockIdx.x * 64;
    const int tid = threadIdx.x;
    const int tx = tid & 15, ty = tid >> 4;
    const float* Wh = W + (size_t)h * K * 64;

    float acc[4][4];
#pragma unroll
    for (int i = 0; i < 4; i++)
#pragma unroll
        for (int j = 0; j < 4; j++) acc[i][j] = 0.f;

    for (int k0 = 0; k0 < K; k0 += 16) {
#pragma unroll
        for (int i = 0; i < 4; i++) {
            int idx = tid + i * 256;           // 0..1023
            int r = idx >> 4, c = idx & 15;
            Ast[c][r] = in[(size_t)(nb + r) * K + k0 + c];
        }
#pragma unroll
        for (int i = 0; i < 4; i++) {
            int idx = tid + i * 256;
            int r = idx >> 6, c = idx & 63;
            Bs[r][c] = Wh[(size_t)(k0 + r) * 64 + c];
        }
        __syncthreads();
#pragma unroll
        for (int kk = 0; kk < 16; kk++) {
            float4 a4 = *reinterpret_cast<const float4*>(&Ast[kk][ty * 4]);
            float4 b4 = *reinterpret_cast<const float4*>(&Bs[kk][tx * 4]);
            float a[4] = {a4.x, a4.y, a4.z, a4.w};
            float b[4] = {b4.x, b4.y, b4.z, b4.w};
#pragma unroll
            for (int i = 0; i < 4; i++)
#pragma unroll
                for (int j = 0; j < 4; j++) acc[i][j] = fmaf(a[i], b[j], acc[i][j]);
        }
        __syncthreads();
    }
#pragma unroll
    for (int i = 0; i < 4; i++) {
        int n = nb + ty * 4 + i;
        float4 v = make_float4(acc[i][0], acc[i][1], acc[i][2], acc[i][3]);
        *reinterpret_cast<float4*>(&hfeat[((size_t)h * N_NODES + n) * 64 + tx * 4]) = v;
#pragma unroll
        for (int jj = 0; jj < 4; jj++)
            h16T[((size_t)h * 64 + tx * 4 + jj) * N_NODES + n] = __float2half_rn(acc[i][jj]);
    }
}

// ---------------- e_l, e_r dot products (one warp per (h,n)) ----------------
__global__ void k_elr(const float* __restrict__ hfeat, const float* __restrict__ a,
                      float* __restrict__ el, float* __restrict__ er) {
    const int lane = threadIdx.x & 31;
    const int idx  = blockIdx.x * 8 + (threadIdx.x >> 5);   // idx = h*N + n
    const int h    = idx >> 12;
    const float* hp = hfeat + (size_t)idx * 64;
    const float* ap = a + h * 128;
    float v0 = hp[lane], v1 = hp[lane + 32];
    float sl = v0 * ap[lane]      + v1 * ap[lane + 32];
    float sr = v0 * ap[64 + lane] + v1 * ap[96 + lane];
#pragma unroll
    for (int o = 16; o; o >>= 1) {
        sl += __shfl_xor_sync(0xffffffffu, sl, o);
        sr += __shfl_xor_sync(0xffffffffu, sr, o);
    }
    if (lane == 0) { el[idx] = sl; er[idx] = sr; }
}

// ---------------- per-head max of e_r ----------------
__global__ void k_max(const float* __restrict__ er, float* __restrict__ C) {
    const int h = blockIdx.x;
    __shared__ float sm[32];
    float m = -3.4e38f;
    for (int i = threadIdx.x; i < N_NODES; i += blockDim.x) m = fmaxf(m, er[h * N_NODES + i]);
#pragma unroll
    for (int o = 16; o; o >>= 1) m = fmaxf(m, __shfl_xor_sync(0xffffffffu, m, o));
    if ((threadIdx.x & 31) == 0) sm[threadIdx.x >> 5] = m;
    __syncthreads();
    if (threadIdx.x < 32) {
        float v = sm[threadIdx.x];
#pragma unroll
        for (int o = 16; o; o >>= 1) v = fmaxf(v, __shfl_xor_sync(0xffffffffu, v, o));
        if (threadIdx.x == 0) C[h] = v;
    }
}

// ---------------- P,Q,G1,G2 (O(N) exps) ----------------
__global__ void k_pqg(const float* __restrict__ el, const float* __restrict__ er,
                      const float* __restrict__ C,
                      float* __restrict__ P, float* __restrict__ Q,
                      float* __restrict__ G1, float* __restrict__ G2) {
    const int i = blockIdx.x * 256 + threadIdx.x;
    const int h = i >> 12;
    const float c  = C[h];
    const float e_r = er[i], e_l = el[i];
    P[i] = expf(e_r - c);
    Q[i] = expf(0.2f * (e_r - c));
    const float z = e_l + c;
    if (z > 0.f) { G1[i] = 1.f;               G2[i] = expf(-0.8f * z); }
    else         { G1[i] = expf(0.8f * z);    G2[i] = 1.f; }
}

// ---------------- fused flash-style attention: out = (W @ h) / rowsum(W) ----------------
// Pipelined, double-buffered. Correct branch == max(G1*P, G2*Q)  (no compare needed).
struct AttnSmem {
    __half Ws [2][128 * 136];   // double-buffered W tiles (padded)
    __half hTs[2][64 * 136];    // double-buffered h tiles, hT[o][m]
    float  Pall[N_NODES], Qall[N_NODES];
    float  rowsum[128];
};

__device__ __forceinline__ unsigned smem_u32(const void* p) {
    return (unsigned)__cvta_generic_to_shared(p);
}

template<int SPLIT>
__global__ void __launch_bounds__(256) k_attn(
    const __half* __restrict__ h16T,
    const float* __restrict__ Pg, const float* __restrict__ Qg,
    const float* __restrict__ G1g, const float* __restrict__ G2g,
    const unsigned* __restrict__ maskw,
    float* __restrict__ out, int outStride, int applyElu,
    float* __restrict__ part) {
    extern __shared__ char smem_raw[];
    AttnSmem& S = *reinterpret_cast<AttnSmem*>(smem_raw);

    const int head = blockIdx.y;
    const int n0   = blockIdx.x * 128;
    const int tid  = threadIdx.x;
    const int lane = tid & 31, warp = tid >> 5;
    const int brow = tid >> 1;         // W-build row (2 threads/row)
    const int par  = tid & 1;          // which 64-column half this thread builds

    const int hb = head * N_NODES;
    const float g1 = G1g[hb + n0 + brow];
    const float g2 = G2g[hb + n0 + brow];
    float rs = 0.f;

    float acc[8][4];
#pragma unroll
    for (int i = 0; i < 8; i++)
#pragma unroll
        for (int j = 0; j < 4; j++) acc[i][j] = 0.f;

    const __half*   hT   = h16T + (size_t)head * 64 * N_NODES;
    const unsigned* mrow = maskw + (size_t)(n0 + brow) * 128;

    // stage P/Q for the whole m-range once per CTA
    {
        const float4* Ps = reinterpret_cast<const float4*>(Pg + hb);
        const float4* Qs = reinterpret_cast<const float4*>(Qg + hb);
        float4* Pd = reinterpret_cast<float4*>(S.Pall);
        float4* Qd = reinterpret_cast<float4*>(S.Qall);
#pragma unroll
        for (int i = 0; i < 4; i++) { Pd[tid + i * 256] = Ps[tid + i * 256];
                                      Qd[tid + i * 256] = Qs[tid + i * 256]; }
    }
    __syncthreads();

    constexpr int NTILES = (N_NODES / 128) / SPLIT;
    const int jbase = blockIdx.z * NTILES;

    // ---- build one tile (load hT + compute W) into buffer `buf` ----
    auto build = [&](int j, int buf) {
        const int m0 = j * 128;
#pragma unroll
        for (int i = 0; i < 4; i++) {
            int idx = tid + i * 256;
            int r = idx >> 4, c = idx & 15;
            *reinterpret_cast<uint4*>(&S.hTs[buf][r * 136 + c * 8]) =
                *reinterpret_cast<const uint4*>(hT + (size_t)r * N_NODES + m0 + c * 8);
        }
        uint2 mwv = *reinterpret_cast<const uint2*>(mrow + (m0 >> 5) + par * 2);
        uint64_t wm = (uint64_t)mwv.x | ((uint64_t)mwv.y << 32);
        const float2* P2 = reinterpret_cast<const float2*>(S.Pall + m0) + par * 32;
        const float2* Q2 = reinterpret_cast<const float2*>(S.Qall + m0) + par * 32;
        __half* wr = &S.Ws[buf][brow * 136 + par * 64];
#pragma unroll
        for (int g = 0; g < 8; g++) {
            unsigned pk[4];
#pragma unroll
            for (int u = 0; u < 4; u++) {
                const int i = g * 4 + u;
                float2 p = P2[i], q = Q2[i];
                float v0 = fmaxf(g1 * p.x, g2 * q.x);
                float v1 = fmaxf(g1 * p.y, g2 * q.y);
                v0 = ((wm >> (2 * i))     & 1ull) ? v0 : 0.f;
                v1 = ((wm >> (2 * i + 1)) & 1ull) ? v1 : 0.f;
                rs += v0 + v1;
                __half2 hv = __floats2half2_rn(v0, v1);
                pk[u] = *reinterpret_cast<unsigned*>(&hv);
            }
            uint4 pack = make_uint4(pk[0], pk[1], pk[2], pk[3]);
            *reinterpret_cast<uint4*>(wr + g * 8) = pack;
        }
    };

    // ---- MMA on buffer `buf`: [128x128] @ [128x64], fp16 -> fp32 ----
    auto do_mma = [&](int buf) {
#pragma unroll
        for (int kc = 0; kc < 8; kc++) {
            unsigned a0, a1, a2, a3;
            {
                int arow = warp * 16 + (lane & 15);
                int acol = kc * 16 + (lane >> 4) * 8;
                unsigned aaddr = smem_u32(&S.Ws[buf][arow * 136 + acol]);
                asm volatile("ldmatrix.sync.aligned.m8n8.x4.shared.b16 {%0,%1,%2,%3}, [%4];\n"
                             : "=r"(a0), "=r"(a1), "=r"(a2), "=r"(a3) : "r"(aaddr));
            }
#pragma unroll
            for (int ncp = 0; ncp < 4; ncp++) {
                int g = lane >> 3, r = lane & 7;
                int brw  = ncp * 16 + (g >> 1) * 8 + r;
                int bcol = kc * 16 + (g & 1) * 8;
                unsigned baddr = smem_u32(&S.hTs[buf][brw * 136 + bcol]);
                unsigned b0, b1, b2, b3;
                asm volatile("ldmatrix.sync.aligned.m8n8.x4.shared.b16 {%0,%1,%2,%3}, [%4];\n"
                             : "=r"(b0), "=r"(b1), "=r"(b2), "=r"(b3) : "r"(baddr));
                asm volatile(
                    "mma.sync.aligned.m16n8k16.row.col.f32.f16.f16.f32 "
                    "{%0,%1,%2,%3}, {%4,%5,%6,%7}, {%8,%9}, {%0,%1,%2,%3};\n"
                    : "+f"(acc[2 * ncp][0]), "+f"(acc[2 * ncp][1]),
                      "+f"(acc[2 * ncp][2]), "+f"(acc[2 * ncp][3])
                    : "r"(a0), "r"(a1), "r"(a2), "r"(a3), "r"(b0), "r"(b1));
                asm volatile(
                    "mma.sync.aligned.m16n8k16.row.col.f32.f16.f16.f32 "
                    "{%0,%1,%2,%3}, {%4,%5,%6,%7}, {%8,%9}, {%0,%1,%2,%3};\n"
                    : "+f"(acc[2 * ncp + 1][0]), "+f"(acc[2 * ncp + 1][1]),
                      "+f"(acc[2 * ncp + 1][2]), "+f"(acc[2 * ncp + 1][3])
                    : "r"(a0), "r"(a1), "r"(a2), "r"(a3), "r"(b2), "r"(b3));
            }
        }
    };

    // ---- pipelined main loop: build(t+1) overlaps (issue-wise) with mma(t) ----
    build(jbase, 0);
#pragma unroll 1
    for (int t = 0; t < NTILES; t++) {
        __syncthreads();
        if (t + 1 < NTILES) build(jbase + t + 1, (t + 1) & 1);
        do_mma(t & 1);
    }

    // ---- combine rowsums ----
    __syncthreads();
    if (par == 0) S.rowsum[brow] = rs;
    __syncthreads();
    if (par == 1) S.rowsum[brow] += rs;
    __syncthreads();

    const int r_lo = warp * 16 + (lane >> 2);
    if (SPLIT == 1) {
        // ---- epilogue: divide, ELU, store ----
        const float inv_lo = 1.f / S.rowsum[r_lo];
        const float inv_hi = 1.f / S.rowsum[r_lo + 8];
        float* obase = out + (size_t)n0 * outStride + head * 64;
#pragma unroll
        for (int nc = 0; nc < 8; nc++) {
            int col = nc * 8 + 2 * (lane & 3);
            float o0 = acc[nc][0] * inv_lo, o1 = acc[nc][1] * inv_lo;
            float o2 = acc[nc][2] * inv_hi, o3 = acc[nc][3] * inv_hi;
            if (applyElu) {
                o0 = o0 > 0.f ? o0 : expm1f(o0);
                o1 = o1 > 0.f ? o1 : expm1f(o1);
                o2 = o2 > 0.f ? o2 : expm1f(o2);
                o3 = o3 > 0.f ? o3 : expm1f(o3);
            }
            *reinterpret_cast<float2*>(obase + (size_t)r_lo * outStride + col)       = make_float2(o0, o1);
            *reinterpret_cast<float2*>(obase + (size_t)(r_lo + 8) * outStride + col) = make_float2(o2, o3);
        }
    } else {
        // ---- write partial (numerator + rowsum) for split-m combine ----
        float* pbase = part + ((size_t)blockIdx.z * N_NODES + n0) * 68;
#pragma unroll
        for (int nc = 0; nc < 8; nc++) {
            int col = nc * 8 + 2 * (lane & 3);
            *reinterpret_cast<float2*>(pbase + (size_t)r_lo * 68 + col)       = make_float2(acc[nc][0], acc[nc][1]);
            *reinterpret_cast<float2*>(pbase + (size_t)(r_lo + 8) * 68 + col) = make_float2(acc[nc][2], acc[nc][3]);
        }
        if ((lane & 3) == 0) {
            pbase[(size_t)r_lo * 68 + 64]       = S.rowsum[r_lo];
            pbase[(size_t)(r_lo + 8) * 68 + 64] = S.rowsum[r_lo + 8];
        }
    }
}

// ---------------- combine split-m partials (layer 2, no ELU) ----------------
__global__ void k_combine(const float* __restrict__ part, float* __restrict__ out) {
    const int idx = blockIdx.x * 256 + threadIdx.x;    // n*64 + o
    const int n = idx >> 6, o = idx & 63;
    float s = 0.f, r = 0.f;
#pragma unroll
    for (int z = 0; z < 4; z++) {
        s += part[((size_t)z * N_NODES + n) * 68 + o];
        r += part[((size_t)z * N_NODES + n) * 68 + 64];
    }
    out[(size_t)n * 64 + o] = s / r;
}

// ---------------- host orchestration ----------------
struct Scratch {
    unsigned* maskw; float* hfeat; __half* h16T;
    float *el, *er, *C, *P, *Q, *G1, *G2, *buf0, *buf1, *part;
};

static void run_layer(const float* in, int K, const float* W, const float* a, int H,
                      float* outp, int outStride, int applyElu, int split, const Scratch& s) {
    k_feat<<<dim3(K == 128 ? 64 : 64, H), 256>>>(in, W, s.hfeat, s.h16T, K);
    k_elr <<<H * (N_NODES / 8), 256>>>(s.hfeat, a, s.el, s.er);
    k_max <<<H, 1024>>>(s.er, s.C);
    k_pqg <<<H * (N_NODES / 256), 256>>>(s.el, s.er, s.C, s.P, s.Q, s.G1, s.G2);
    if (split == 1) {
        k_attn<1><<<dim3(N_NODES / 128, H, 1), 256, sizeof(AttnSmem)>>>(
            s.h16T, s.P, s.Q, s.G1, s.G2, s.maskw, outp, outStride, applyElu, s.part);
    } else {
        k_attn<4><<<dim3(N_NODES / 128, H, 4), 256, sizeof(AttnSmem)>>>(
            s.h16T, s.P, s.Q, s.G1, s.G2, s.maskw, outp, outStride, applyElu, s.part);
        k_combine<<<N_NODES * 64 / 256, 256>>>(s.part, outp);
    }
}

extern "C" void kernel_launch(void* const* d_in, const int* in_sizes, int n_in,
                              void* d_out, int out_size) {
    (void)in_sizes; (void)n_in; (void)out_size;
    const float* x  = (const float*)d_in[0];
    const int*   adj = (const int*)d_in[1];
    const float* W0 = (const float*)d_in[2];
    const float* a0 = (const float*)d_in[3];
    const float* W1 = (const float*)d_in[4];
    const float* a1 = (const float*)d_in[5];
    const float* W2 = (const float*)d_in[6];
    const float* a2 = (const float*)d_in[7];

    cudaFuncSetAttribute(k_attn<1>, cudaFuncAttributeMaxDynamicSharedMemorySize,
                         (int)sizeof(AttnSmem));
    cudaFuncSetAttribute(k_attn<4>, cudaFuncAttributeMaxDynamicSharedMemorySize,
                         (int)sizeof(AttnSmem));

    Scratch s;
    void* p;
    cudaGetSymbolAddress(&p, g_maskw); s.maskw = (unsigned*)p;
    cudaGetSymbolAddress(&p, g_hfeat); s.hfeat = (float*)p;
    cudaGetSymbolAddress(&p, g_h16T);  s.h16T  = (__half*)p;
    cudaGetSymbolAddress(&p, g_el);    s.el    = (float*)p;
    cudaGetSymbolAddress(&p, g_er);    s.er    = (float*)p;
    cudaGetSymbolAddress(&p, g_C);     s.C     = (float*)p;
    cudaGetSymbolAddress(&p, g_P);     s.P     = (float*)p;
    cudaGetSymbolAddress(&p, g_Q);     s.Q     = (float*)p;
    cudaGetSymbolAddress(&p, g_G1);    s.G1    = (float*)p;
    cudaGetSymbolAddress(&p, g_G2);    s.G2    = (float*)p;
    cudaGetSymbolAddress(&p, g_buf0);  s.buf0  = (float*)p;
    cudaGetSymbolAddress(&p, g_buf1);  s.buf1  = (float*)p;
    cudaGetSymbolAddress(&p, g_part);  s.part  = (float*)p;

    k_mask<<<N_NODES, 1024>>>(adj, s.maskw);

    run_layer(x,      128, W0, a0, 4, s.buf0,         256, 1, 1, s);
    run_layer(s.buf0, 256, W1, a1, 4, s.buf1,         256, 1, 1, s);
    run_layer(s.buf1, 256, W2, a2, 1, (float*)d_out,   64, 0, 4, s);
}

// round 5
// speedup vs baseline: 2.2079x; 1.5334x over previous
#include <cuda_runtime.h>
#include <cuda_fp16.h>
#include <cstdint>

#define N_NODES 4096
#define MAXH 4

// ---------------- scratch (static device globals; no allocation) ----------------
__device__ unsigned g_maskw[N_NODES * 128];            // 2 MB adjacency bitmask
__device__ __half   g_h16T [MAXH * 64 * N_NODES];      // per-head features fp16, transposed [h][o][n]
__device__ float    g_el[MAXH * N_NODES], g_er[MAXH * N_NODES];
__device__ __half   g_Ph[MAXH * N_NODES], g_Qh[MAXH * N_NODES];
__device__ float    g_G1[MAXH * N_NODES], g_G2[MAXH * N_NODES];
__device__ float    g_buf0[N_NODES * 256];
__device__ float    g_buf1[N_NODES * 256];
__device__ float    g_part[4 * N_NODES * 68];          // split-m partials for layer 2

#define PACK2(d, lo, hi) asm("mov.b64 %0, {%1, %2};" : "=l"(d) : "f"(lo), "f"(hi))
#define UNPACK2(lo, hi, s) asm("mov.b64 {%0, %1}, %2;" : "=f"(lo), "=f"(hi) : "l"(s))
#define FMA2(acc, A, B) asm("fma.rn.f32x2 %0, %1, %2, %0;" : "+l"(acc) : "l"(A), "l"(B))

// ---------------- adjacency -> bitmask ----------------
__global__ void k_mask(const int* __restrict__ adj, unsigned* __restrict__ maskw) {
    int n = blockIdx.x;
    int tid = threadIdx.x;
    const int* row = adj + (size_t)n * N_NODES;
#pragma unroll
    for (int it = 0; it < 4; it++) {
        int m = it * 1024 + tid;
        unsigned b = __ballot_sync(0xffffffffu, row[m] > 0);
        if ((tid & 31) == 0) maskw[n * 128 + (m >> 5)] = b;
    }
}

// ---------------- feature GEMM + fused e_l/e_r epilogue ----------------
// h[h][n][o] = in[n][:K] @ W[h][:K][o];  el/er = h . a_{l,r}
__global__ void k_feat(const float* __restrict__ in, const float* __restrict__ W,
                       const float* __restrict__ a,
                       __half* __restrict__ h16T,
                       float* __restrict__ el, float* __restrict__ er, int K) {
    __shared__ float Ast[16][68];   // k-major (transposed) for vector LDS
    __shared__ float Bs[16][68];
    const int h  = blockIdx.y;
    const int nb = blockIdx.x * 64;
    const int tid = threadIdx.x;
    const int tx = tid & 15, ty = tid >> 4;
    const float* Wh = W + (size_t)h * K * 64;

    unsigned long long acc2[4][2];
#pragma unroll
    for (int i = 0; i < 4; i++) { acc2[i][0] = 0ull; acc2[i][1] = 0ull; }

    for (int k0 = 0; k0 < K; k0 += 16) {
#pragma unroll
        for (int i = 0; i < 4; i++) {
            int idx = tid + i * 256;           // 0..1023
            int r = idx >> 4, c = idx & 15;
            Ast[c][r] = in[(size_t)(nb + r) * K + k0 + c];
        }
#pragma unroll
        for (int i = 0; i < 4; i++) {
            int idx = tid + i * 256;
            int r = idx >> 6, c = idx & 63;
            Bs[r][c] = Wh[(size_t)(k0 + r) * 64 + c];
        }
        __syncthreads();
#pragma unroll
        for (int kk = 0; kk < 16; kk++) {
            float4 a4 = *reinterpret_cast<const float4*>(&Ast[kk][ty * 4]);
            float4 b4 = *reinterpret_cast<const float4*>(&Bs[kk][tx * 4]);
            unsigned long long b01, b23, aa;
            PACK2(b01, b4.x, b4.y);
            PACK2(b23, b4.z, b4.w);
            PACK2(aa, a4.x, a4.x); FMA2(acc2[0][0], aa, b01); FMA2(acc2[0][1], aa, b23);
            PACK2(aa, a4.y, a4.y); FMA2(acc2[1][0], aa, b01); FMA2(acc2[1][1], aa, b23);
            PACK2(aa, a4.z, a4.z); FMA2(acc2[2][0], aa, b01); FMA2(acc2[2][1], aa, b23);
            PACK2(aa, a4.w, a4.w); FMA2(acc2[3][0], aa, b01); FMA2(acc2[3][1], aa, b23);
        }
        __syncthreads();
    }

    float acc[4][4];
#pragma unroll
    for (int i = 0; i < 4; i++) {
        UNPACK2(acc[i][0], acc[i][1], acc2[i][0]);
        UNPACK2(acc[i][2], acc[i][3], acc2[i][1]);
    }

    // fp16 transposed store
#pragma unroll
    for (int i = 0; i < 4; i++) {
        int n = nb + ty * 4 + i;
#pragma unroll
        for (int jj = 0; jj < 4; jj++)
            h16T[((size_t)h * 64 + tx * 4 + jj) * N_NODES + n] = __float2half_rn(acc[i][jj]);
    }

    // fused e_l/e_r: dot with a_l/a_r, reduce over the 16 lanes covering o
    float al[4], ar[4];
#pragma unroll
    for (int j = 0; j < 4; j++) {
        al[j] = a[h * 128 + tx * 4 + j];
        ar[j] = a[h * 128 + 64 + tx * 4 + j];
    }
#pragma unroll
    for (int i = 0; i < 4; i++) {
        float sl = 0.f, sr = 0.f;
#pragma unroll
        for (int j = 0; j < 4; j++) { sl = fmaf(acc[i][j], al[j], sl); sr = fmaf(acc[i][j], ar[j], sr); }
#pragma unroll
        for (int o = 1; o < 16; o <<= 1) {
            sl += __shfl_xor_sync(0xffffffffu, sl, o);
            sr += __shfl_xor_sync(0xffffffffu, sr, o);
        }
        if (tx == 0) {
            el[(size_t)h * N_NODES + nb + ty * 4 + i] = sl;
            er[(size_t)h * N_NODES + nb + ty * 4 + i] = sr;
        }
    }
}

// ---------------- fused per-head max + P,Q (half), G1,G2 (fp32) ----------------
__global__ void k_maxpqg(const float* __restrict__ el, const float* __restrict__ er,
                         float* __restrict__ G1, float* __restrict__ G2,
                         __half* __restrict__ Ph, __half* __restrict__ Qh) {
    const int h = blockIdx.x;
    const int base = h * N_NODES;
    __shared__ float sm[32];
    __shared__ float csh;
    float m = -3.4e38f;
    for (int i = threadIdx.x; i < N_NODES; i += 1024) m = fmaxf(m, er[base + i]);
#pragma unroll
    for (int o = 16; o; o >>= 1) m = fmaxf(m, __shfl_xor_sync(0xffffffffu, m, o));
    if ((threadIdx.x & 31) == 0) sm[threadIdx.x >> 5] = m;
    __syncthreads();
    if (threadIdx.x < 32) {
        float v = sm[threadIdx.x];
#pragma unroll
        for (int o = 16; o; o >>= 1) v = fmaxf(v, __shfl_xor_sync(0xffffffffu, v, o));
        if (threadIdx.x == 0) csh = v;
    }
    __syncthreads();
    const float c = csh;
    for (int i = threadIdx.x; i < N_NODES; i += 1024) {
        const float e_r = er[base + i], e_l = el[base + i];
        Ph[base + i] = __float2half_rn(expf(e_r - c));
        Qh[base + i] = __float2half_rn(expf(0.2f * (e_r - c)));
        const float z = e_l + c;
        if (z > 0.f) { G1[base + i] = 1.f;            G2[base + i] = expf(-0.8f * z); }
        else         { G1[base + i] = expf(0.8f * z); G2[base + i] = 1.f; }
    }
}

// ---------------- fused flash-style attention: out = (W @ h) / rowsum(W) ----------------
struct AttnSmem {
    __half Ws [2][128 * 136];   // double-buffered W tiles (padded)
    __half hTs[2][64 * 136];    // double-buffered h tiles, hT[o][m]
    __half Ppk[N_NODES], Qpk[N_NODES];
    uint2  lut[16 * 8];         // nibble -> two half2 {0/1} masks, x8 bank copies
};

__device__ __forceinline__ unsigned smem_u32(const void* p) {
    return (unsigned)__cvta_generic_to_shared(p);
}
__device__ __forceinline__ __half2 u2h(unsigned u) { return *reinterpret_cast<__half2*>(&u); }
__device__ __forceinline__ unsigned h2u(__half2 h) { return *reinterpret_cast<unsigned*>(&h); }

template<int SPLIT>
__global__ void __launch_bounds__(256) k_attn(
    const __half* __restrict__ h16T,
    const __half* __restrict__ Phg, const __half* __restrict__ Qhg,
    const float* __restrict__ G1g, const float* __restrict__ G2g,
    const unsigned* __restrict__ maskw,
    float* __restrict__ out, int outStride, int applyElu,
    float* __restrict__ part) {
    extern __shared__ char smem_raw[];
    AttnSmem& S = *reinterpret_cast<AttnSmem*>(smem_raw);

    const int head = blockIdx.y;
    const int n0   = blockIdx.x * 128;
    const int tid  = threadIdx.x;
    const int lane = tid & 31, warp = tid >> 5;
    const int brow = tid >> 1;         // W-build row (2 threads/row)
    const int par  = tid & 1;          // which 64-column half this thread builds
    const int hb = head * N_NODES;

    // stage packed P/Q + mask LUT
    {
        const uint4* Ps = reinterpret_cast<const uint4*>(Phg + hb);
        const uint4* Qs = reinterpret_cast<const uint4*>(Qhg + hb);
        uint4* Pd = reinterpret_cast<uint4*>(S.Ppk);
        uint4* Qd = reinterpret_cast<uint4*>(S.Qpk);
        Pd[tid] = Ps[tid]; Pd[tid + 256] = Ps[tid + 256];
        Qd[tid] = Qs[tid]; Qd[tid + 256] = Qs[tid + 256];
        if (tid < 128) {
            unsigned nib = tid >> 3;
            unsigned lo = ((nib & 1u) ? 0x3C00u : 0u) | ((nib & 2u) ? 0x3C000000u : 0u);
            unsigned hi = ((nib & 4u) ? 0x3C00u : 0u) | ((nib & 8u) ? 0x3C000000u : 0u);
            S.lut[tid] = make_uint2(lo, hi);
        }
    }
    const __half2 g1h2 = __float2half2_rn(G1g[hb + n0 + brow]);
    const __half2 g2h2 = __float2half2_rn(G2g[hb + n0 + brow]);
    __syncthreads();

    float acc[8][4];
#pragma unroll
    for (int i = 0; i < 8; i++)
#pragma unroll
        for (int j = 0; j < 4; j++) acc[i][j] = 0.f;
    float acc_rs[4] = {0.f, 0.f, 0.f, 0.f};   // rowsum via ones-column MMA

    const __half*   hT   = h16T + (size_t)head * 64 * N_NODES;
    const unsigned* mrow = maskw + (size_t)(n0 + brow) * 128;
    const int lsel = lane & 7;

    constexpr int NTILES = (N_NODES / 128) / SPLIT;
    const int jbase = blockIdx.z * NTILES;

    // ---- build one tile (load hT + compute W in half2) into buffer `buf` ----
    auto build = [&](int j, int buf) {
        const int m0 = j * 128;
#pragma unroll
        for (int i = 0; i < 4; i++) {
            int idx = tid + i * 256;
            int r = idx >> 4, c = idx & 15;
            *reinterpret_cast<uint4*>(&S.hTs[buf][r * 136 + c * 8]) =
                *reinterpret_cast<const uint4*>(hT + (size_t)r * N_NODES + m0 + c * 8);
        }
        uint2 mwv = *reinterpret_cast<const uint2*>(mrow + (m0 >> 5) + par * 2);
        uint64_t wm = ((uint64_t)mwv.y << 32) | mwv.x;
        const uint4* Pp = reinterpret_cast<const uint4*>(S.Ppk + m0 + par * 64);
        const uint4* Qp = reinterpret_cast<const uint4*>(S.Qpk + m0 + par * 64);
        __half* wr = &S.Ws[buf][brow * 136 + par * 64];
#pragma unroll
        for (int g = 0; g < 8; g++) {
            uint4 pv = Pp[g], qv = Qp[g];
            unsigned by = (unsigned)(wm >> (8 * g)) & 0xffu;
            uint2 mk0 = S.lut[((by & 15u) << 3) | lsel];
            uint2 mk1 = S.lut[((by >> 4) << 3) | lsel];
            __half2 w0 = __hmul2(__hmax2(__hmul2(g1h2, u2h(pv.x)), __hmul2(g2h2, u2h(qv.x))), u2h(mk0.x));
            __half2 w1 = __hmul2(__hmax2(__hmul2(g1h2, u2h(pv.y)), __hmul2(g2h2, u2h(qv.y))), u2h(mk0.y));
            __half2 w2 = __hmul2(__hmax2(__hmul2(g1h2, u2h(pv.z)), __hmul2(g2h2, u2h(qv.z))), u2h(mk1.x));
            __half2 w3 = __hmul2(__hmax2(__hmul2(g1h2, u2h(pv.w)), __hmul2(g2h2, u2h(qv.w))), u2h(mk1.y));
            *reinterpret_cast<uint4*>(wr + g * 8) = make_uint4(h2u(w0), h2u(w1), h2u(w2), h2u(w3));
        }
    };

    // ---- MMA on buffer `buf`: [128x128] @ [128x64] + ones-column rowsum ----
    auto do_mma = [&](int buf) {
        const unsigned bone = 0x3C003C00u;   // half2(1,1)
#pragma unroll
        for (int kc = 0; kc < 8; kc++) {
            unsigned a0, a1, a2, a3;
            {
                int arow = warp * 16 + (lane & 15);
                int acol = kc * 16 + (lane >> 4) * 8;
                unsigned aaddr = smem_u32(&S.Ws[buf][arow * 136 + acol]);
                asm volatile("ldmatrix.sync.aligned.m8n8.x4.shared.b16 {%0,%1,%2,%3}, [%4];\n"
                             : "=r"(a0), "=r"(a1), "=r"(a2), "=r"(a3) : "r"(aaddr));
            }
            asm volatile(
                "mma.sync.aligned.m16n8k16.row.col.f32.f16.f16.f32 "
                "{%0,%1,%2,%3}, {%4,%5,%6,%7}, {%8,%9}, {%0,%1,%2,%3};\n"
                : "+f"(acc_rs[0]), "+f"(acc_rs[1]), "+f"(acc_rs[2]), "+f"(acc_rs[3])
                : "r"(a0), "r"(a1), "r"(a2), "r"(a3), "r"(bone), "r"(bone));
#pragma unroll
            for (int ncp = 0; ncp < 4; ncp++) {
                int g = lane >> 3, r = lane & 7;
                int brw  = ncp * 16 + (g >> 1) * 8 + r;
                int bcol = kc * 16 + (g & 1) * 8;
                unsigned baddr = smem_u32(&S.hTs[buf][brw * 136 + bcol]);
                unsigned b0, b1, b2, b3;
                asm volatile("ldmatrix.sync.aligned.m8n8.x4.shared.b16 {%0,%1,%2,%3}, [%4];\n"
                             : "=r"(b0), "=r"(b1), "=r"(b2), "=r"(b3) : "r"(baddr));
                asm volatile(
                    "mma.sync.aligned.m16n8k16.row.col.f32.f16.f16.f32 "
                    "{%0,%1,%2,%3}, {%4,%5,%6,%7}, {%8,%9}, {%0,%1,%2,%3};\n"
                    : "+f"(acc[2 * ncp][0]), "+f"(acc[2 * ncp][1]),
                      "+f"(acc[2 * ncp][2]), "+f"(acc[2 * ncp][3])
                    : "r"(a0), "r"(a1), "r"(a2), "r"(a3), "r"(b0), "r"(b1));
                asm volatile(
                    "mma.sync.aligned.m16n8k16.row.col.f32.f16.f16.f32 "
                    "{%0,%1,%2,%3}, {%4,%5,%6,%7}, {%8,%9}, {%0,%1,%2,%3};\n"
                    : "+f"(acc[2 * ncp + 1][0]), "+f"(acc[2 * ncp + 1][1]),
                      "+f"(acc[2 * ncp + 1][2]), "+f"(acc[2 * ncp + 1][3])
                    : "r"(a0), "r"(a1), "r"(a2), "r"(a3), "r"(b2), "r"(b3));
            }
        }
    };

    // ---- pipelined main loop: build(t+1) overlaps (issue-wise) with mma(t) ----
    build(jbase, 0);
#pragma unroll 1
    for (int t = 0; t < NTILES; t++) {
        __syncthreads();
        if (t + 1 < NTILES) build(jbase + t + 1, (t + 1) & 1);
        do_mma(t & 1);
    }

    const int r_lo = warp * 16 + (lane >> 2);
    if (SPLIT == 1) {
        // ---- epilogue: divide (rowsum from ones-MMA), ELU, store ----
        const float inv_lo = 1.f / acc_rs[0];
        const float inv_hi = 1.f / acc_rs[2];
        float* obase = out + (size_t)n0 * outStride + head * 64;
#pragma unroll
        for (int nc = 0; nc < 8; nc++) {
            int col = nc * 8 + 2 * (lane & 3);
            float o0 = acc[nc][0] * inv_lo, o1 = acc[nc][1] * inv_lo;
            float o2 = acc[nc][2] * inv_hi, o3 = acc[nc][3] * inv_hi;
            if (applyElu) {
                o0 = o0 > 0.f ? o0 : expm1f(o0);
                o1 = o1 > 0.f ? o1 : expm1f(o1);
                o2 = o2 > 0.f ? o2 : expm1f(o2);
                o3 = o3 > 0.f ? o3 : expm1f(o3);
            }
            *reinterpret_cast<float2*>(obase + (size_t)r_lo * outStride + col)       = make_float2(o0, o1);
            *reinterpret_cast<float2*>(obase + (size_t)(r_lo + 8) * outStride + col) = make_float2(o2, o3);
        }
    } else {
        // ---- write partial (numerator + rowsum) for split-m combine ----
        float* pbase = part + ((size_t)blockIdx.z * N_NODES + n0) * 68;
#pragma unroll
        for (int nc = 0; nc < 8; nc++) {
            int col = nc * 8 + 2 * (lane & 3);
            *reinterpret_cast<float2*>(pbase + (size_t)r_lo * 68 + col)       = make_float2(acc[nc][0], acc[nc][1]);
            *reinterpret_cast<float2*>(pbase + (size_t)(r_lo + 8) * 68 + col) = make_float2(acc[nc][2], acc[nc][3]);
        }
        if ((lane & 3) == 0) {
            pbase[(size_t)r_lo * 68 + 64]       = acc_rs[0];
            pbase[(size_t)(r_lo + 8) * 68 + 64] = acc_rs[2];
        }
    }
}

// ---------------- combine split-m partials (layer 2, no ELU) ----------------
__global__ void k_combine(const float* __restrict__ part, float* __restrict__ out) {
    const int idx = blockIdx.x * 256 + threadIdx.x;    // n*64 + o
    const int n = idx >> 6, o = idx & 63;
    float s = 0.f, r = 0.f;
#pragma unroll
    for (int z = 0; z < 4; z++) {
        s += part[((size_t)z * N_NODES + n) * 68 + o];
        r += part[((size_t)z * N_NODES + n) * 68 + 64];
    }
    out[(size_t)n * 64 + o] = s / r;
}

// ---------------- host orchestration ----------------
struct Scratch {
    unsigned* maskw; __half* h16T;
    float *el, *er, *G1, *G2, *buf0, *buf1, *part;
    __half *Ph, *Qh;
};

static void run_layer(const float* in, int K, const float* W, const float* a, int H,
                      float* outp, int outStride, int applyElu, int split, const Scratch& s) {
    k_feat<<<dim3(64, H), 256>>>(in, W, a, s.h16T, s.el, s.er, K);
    k_maxpqg<<<H, 1024>>>(s.el, s.er, s.G1, s.G2, s.Ph, s.Qh);
    if (split == 1) {
        k_attn<1><<<dim3(N_NODES / 128, H, 1), 256, sizeof(AttnSmem)>>>(
            s.h16T, s.Ph, s.Qh, s.G1, s.G2, s.maskw, outp, outStride, applyElu, s.part);
    } else {
        k_attn<4><<<dim3(N_NODES / 128, H, 4), 256, sizeof(AttnSmem)>>>(
            s.h16T, s.Ph, s.Qh, s.G1, s.G2, s.maskw, outp, outStride, applyElu, s.part);
        k_combine<<<N_NODES * 64 / 256, 256>>>(s.part, outp);
    }
}

extern "C" void kernel_launch(void* const* d_in, const int* in_sizes, int n_in,
                              void* d_out, int out_size) {
    (void)in_sizes; (void)n_in; (void)out_size;
    const float* x  = (const float*)d_in[0];
    const int*   adj = (const int*)d_in[1];
    const float* W0 = (const float*)d_in[2];
    const float* a0 = (const float*)d_in[3];
    const float* W1 = (const float*)d_in[4];
    const float* a1 = (const float*)d_in[5];
    const float* W2 = (const float*)d_in[6];
    const float* a2 = (const float*)d_in[7];

    cudaFuncSetAttribute(k_attn<1>, cudaFuncAttributeMaxDynamicSharedMemorySize,
                         (int)sizeof(AttnSmem));
    cudaFuncSetAttribute(k_attn<4>, cudaFuncAttributeMaxDynamicSharedMemorySize,
                         (int)sizeof(AttnSmem));

    Scratch s;
    void* p;
    cudaGetSymbolAddress(&p, g_maskw); s.maskw = (unsigned*)p;
    cudaGetSymbolAddress(&p, g_h16T);  s.h16T  = (__half*)p;
    cudaGetSymbolAddress(&p, g_el);    s.el    = (float*)p;
    cudaGetSymbolAddress(&p, g_er);    s.er    = (float*)p;
    cudaGetSymbolAddress(&p, g_G1);    s.G1    = (float*)p;
    cudaGetSymbolAddress(&p, g_G2);    s.G2    = (float*)p;
    cudaGetSymbolAddress(&p, g_buf0);  s.buf0  = (float*)p;
    cudaGetSymbolAddress(&p, g_buf1);  s.buf1  = (float*)p;
    cudaGetSymbolAddress(&p, g_part);  s.part  = (float*)p;
    cudaGetSymbolAddress(&p, g_Ph);    s.Ph    = (__half*)p;
    cudaGetSymbolAddress(&p, g_Qh);    s.Qh    = (__half*)p;

    k_mask<<<N_NODES, 1024>>>(adj, s.maskw);

    run_layer(x,      128, W0, a0, 4, s.buf0,         256, 1, 1, s);
    run_layer(s.buf0, 256, W1, a1, 4, s.buf1,         256, 1, 1, s);
    run_layer(s.buf1, 256, W2, a2, 1, (float*)d_out,   64, 0, 4, s);
}